// round 16
// baseline (speedup 1.0000x reference)
#include <cuda_runtime.h>
#include <cuda.h>
#include <cuda_bf16.h>
#include <cuda_fp16.h>
#include <math.h>
#include <stdint.h>

// ---------------------------------------------------------------------------
// CircleLoss, bulk-copy edition v2 (deadlock-safe mbarrier protocol):
//   1) sort_labels : parallel dtype detect + warp-scan stable counting sort
//   2) to_fp16p    : gather-permuted E -> fp16 scratch
//   3) gemm_fused  : triangular grid (528 CTAs), 512 threads (16 warps of
//                    32x32), BK=64, 3-stage pipeline fed by cp.async.bulk
//                    (128B/row, per-thread arrive.expect_tx), ldmatrix feeds,
//                    row+mirror-col L-form partials. 32 warps/SM.
//   4) combine     : 512 x 256, branch-free warp LSE, ticketed last block
//                    folds block sums -> out[0..3]
// ---------------------------------------------------------------------------

#define MAXB 4096
#define MAXD 512

__device__ __half g_eth[MAXB * MAXD];          // 4 MB permuted fp16 embeddings
__device__ float  g_part[MAXB * 32 * 8];       // 4.2 MB partial states (L-form)
__device__ float4 g_bsum[MAXB / 8];            // per-combine-block sums
__device__ int    g_perm[MAXB];
__device__ int    g_cs[MAXB];
__device__ int    g_ce[MAXB];
__device__ int    g_cnt = 0;                   // combine completion ticket

#define SCALE_C   32.0f
#define MARGIN_P  0.75f
#define MARGIN_N  0.25f
#define OPT_P     1.25f
#define OPT_N     (-0.25f)
#define THETA_C   0.25f
#define NEG_INF   (-INFINITY)

// ------------------------------ helpers ------------------------------------
__device__ __forceinline__ uint32_t smem_u32(const void* p) {
    uint32_t a;
    asm("{ .reg .u64 t; cvta.to.shared.u64 t, %1; cvt.u32.u64 %0, t; }"
        : "=r"(a) : "l"(p));
    return a;
}
#define MBAR_INIT(a, c) \
    asm volatile("mbarrier.init.shared.b64 [%0], %1;" :: "r"(a), "r"((uint32_t)(c)) : "memory")
#define MBAR_ARRIVE_EXPECT(a, bytes) \
    asm volatile("mbarrier.arrive.expect_tx.shared.b64 _, [%0], %1;" \
                 :: "r"(a), "r"((uint32_t)(bytes)) : "memory")
#define MBAR_WAIT(a, par) do {                                                  \
    uint32_t _m = (a), _p = (par);                                              \
    asm volatile("{\n\t.reg .pred P;\n\tWL_%=:\n\t"                             \
        "mbarrier.try_wait.parity.acquire.cta.shared::cta.b64 P, [%0], %1, 0x989680;\n\t" \
        "@P bra.uni WD_%=;\n\tbra.uni WL_%=;\n\tWD_%=:\n\t}"                    \
        :: "r"(_m), "r"(_p) : "memory");                                        \
} while (0)
#define FENCE_PROXY() asm volatile("fence.proxy.async.shared::cta;" ::: "memory")
__device__ __forceinline__ void bulk_cp(uint32_t dst, const void* src,
                                        uint32_t bytes, uint32_t mbar) {
    asm volatile(
        "cp.async.bulk.shared::cluster.global.mbarrier::complete_tx::bytes "
        "[%0], [%1], %2, [%3];"
        :: "r"(dst), "l"(src), "r"(bytes), "r"(mbar) : "memory");
}
__device__ __forceinline__ void ldm_x4(uint32_t* r, uint32_t addr) {
    asm volatile("ldmatrix.sync.aligned.m8n8.x4.shared.b16 {%0,%1,%2,%3}, [%4];"
        : "=r"(r[0]), "=r"(r[1]), "=r"(r[2]), "=r"(r[3]) : "r"(addr));
}
__device__ __forceinline__ void mma_f16_frag(float* d, const uint32_t* a, const uint32_t* b) {
    asm volatile(
        "mma.sync.aligned.m16n8k16.row.col.f32.f16.f16.f32 "
        "{%0,%1,%2,%3}, {%4,%5,%6,%7}, {%8,%9}, {%0,%1,%2,%3};"
        : "+f"(d[0]), "+f"(d[1]), "+f"(d[2]), "+f"(d[3])
        : "r"(a[0]), "r"(a[1]), "r"(a[2]), "r"(a[3]), "r"(b[0]), "r"(b[1]));
}
__device__ __forceinline__ void lse_add(float& m, float& s, float v) {
    if (v > m) { s = s * expf(m - v) + 1.0f; m = v; }
    else       { s += expf(v - m); }
}
__device__ __forceinline__ void lse_merge(float& m1, float& s1, float m2, float s2) {
    if (m2 == NEG_INF) return;
    if (m2 > m1) { s1 = s1 * expf(m1 - m2) + s2; m1 = m2; }
    else         { s1 += s2 * expf(m2 - m1); }
}
__device__ __forceinline__ float lse_close(float m, float s) {
    return (m == NEG_INF) ? NEG_INF : m + logf(s);
}

struct St {
    float pmin, nmax, m1, s1, m2, s2, m3, s3, m4, s4;
    __device__ __forceinline__ void init() {
        pmin = INFINITY; nmax = NEG_INF;
        m1 = m2 = m3 = m4 = NEG_INF; s1 = s2 = s3 = s4 = 0.f;
    }
    __device__ __forceinline__ void upd(float s, int j, int cs, int ce) {
        if (j >= cs && j < ce) {                       // positive (incl. self)
            pmin = fminf(pmin, s);
            if (s < MARGIN_P) {
                float ip = -SCALE_C * fmaxf(OPT_P - s, 0.0f) * (s - MARGIN_P);
                lse_add(m2, s2, ip);
                if (s + THETA_C < MARGIN_P) lse_add(m1, s1, ip);
            }
        } else {
            nmax = fmaxf(nmax, s);
            if (s > MARGIN_N) {
                float in_ = SCALE_C * fmaxf(s - OPT_N, 0.0f) * (s - MARGIN_N);
                lse_add(m4, s4, in_);
                if (s - THETA_C > MARGIN_N) lse_add(m3, s3, in_);
            }
        }
    }
    __device__ __forceinline__ void mergeShfl(int xorMask) {
        const unsigned FM = 0xffffffffu;
        pmin = fminf(pmin, __shfl_xor_sync(FM, pmin, xorMask));
        nmax = fmaxf(nmax, __shfl_xor_sync(FM, nmax, xorMask));
        float mm, ss;
        mm = __shfl_xor_sync(FM, m1, xorMask); ss = __shfl_xor_sync(FM, s1, xorMask);
        lse_merge(m1, s1, mm, ss);
        mm = __shfl_xor_sync(FM, m2, xorMask); ss = __shfl_xor_sync(FM, s2, xorMask);
        lse_merge(m2, s2, mm, ss);
        mm = __shfl_xor_sync(FM, m3, xorMask); ss = __shfl_xor_sync(FM, s3, xorMask);
        lse_merge(m3, s3, mm, ss);
        mm = __shfl_xor_sync(FM, m4, xorMask); ss = __shfl_xor_sync(FM, s4, xorMask);
        lse_merge(m4, s4, mm, ss);
    }
    // L-form store: 8 floats = pmin, nmax, L1..L4, pad, pad
    __device__ __forceinline__ void storeL(float* p) const {
        ((float4*)p)[0] = make_float4(pmin, nmax, lse_close(m1, s1), lse_close(m2, s2));
        ((float4*)p)[1] = make_float4(lse_close(m3, s3), lse_close(m4, s4), 0.f, 0.f);
    }
};

// ---------------------- parallel deterministic sort -------------------------
#define NC 128
#define NCH 256
#define OFF_HIST  (MAXB * 4)
#define OFF_CTOT  (OFF_HIST + NC * NCH * 2)
#define OFF_CST   (OFF_CTOT + NC * 4)
#define SORT_SMEM (OFF_CST + (NC + 1) * 4 + 64)

__global__ void sort_labels(const void* __restrict__ lab, int B) {
    extern __shared__ char sms[];
    int* slab = (int*)sms;
    unsigned short* hist = (unsigned short*)(sms + OFF_HIST);
    int* ctot   = (int*)(sms + OFF_CTOT);
    int* cstart = (int*)(sms + OFF_CST);

    const int t = threadIdx.x;
    const int lane = t & 31, w = t >> 5;
    const int chk = B / NCH;
    const unsigned FM = 0xffffffffu;

    __shared__ int is64;
    {
        const int nProbe = (B < 64) ? B : 64;
        int ok = 1;
        if (t < nProbe) {
            long long v = ((const long long*)lab)[t];
            ok = (v >= 0 && v < (long long)B);
        }
        unsigned m0 = __ballot_sync(FM, ok);
        __shared__ unsigned mball[2];
        if (w < 2 && lane == 0) mball[w] = m0;
        __syncthreads();
        if (t == 0) is64 = (mball[0] == FM) && (mball[1] == FM);
        __syncthreads();
    }
    if (is64) {
        const long long* p = (const long long*)lab;
        for (int i = t; i < B; i += NCH) slab[i] = (int)p[i];
    } else {
        const int* p = (const int*)lab;
        for (int i = t; i < B; i += NCH) slab[i] = p[i];
    }
    for (int i = t; i < NC * NCH / 2; i += NCH) ((uint32_t*)hist)[i] = 0;
    __syncthreads();

    for (int k = 0; k < chk; k++) hist[slab[t * chk + k] * NCH + t]++;
    __syncthreads();

    for (int ci = 0; ci < NC / 8; ci++) {
        const int c = w + 8 * ci;
        uint32_t* hp = (uint32_t*)&hist[c * NCH + lane * 8];
        uint4 q = *(uint4*)hp;
        unsigned v[8] = { q.x & 0xffffu, q.x >> 16, q.y & 0xffffu, q.y >> 16,
                          q.z & 0xffffu, q.z >> 16, q.w & 0xffffu, q.w >> 16 };
        unsigned e[8]; unsigned s = 0;
#pragma unroll
        for (int j = 0; j < 8; j++) { e[j] = s; s += v[j]; }
        unsigned run = s;
#pragma unroll
        for (int off = 1; off < 32; off <<= 1) {
            unsigned n = __shfl_up_sync(FM, run, off);
            if (lane >= off) run += n;
        }
        const unsigned laneExc = run - s;
#pragma unroll
        for (int j = 0; j < 8; j++) e[j] += laneExc;
        *(uint4*)hp = make_uint4(e[0] | (e[1] << 16), e[2] | (e[3] << 16),
                                 e[4] | (e[5] << 16), e[6] | (e[7] << 16));
        if (lane == 31) ctot[c] = (int)run;
    }
    __syncthreads();

    if (w == 0) {
        int v0 = ctot[lane * 4 + 0], v1 = ctot[lane * 4 + 1];
        int v2 = ctot[lane * 4 + 2], v3 = ctot[lane * 4 + 3];
        int s = v0 + v1 + v2 + v3;
        int run = s;
#pragma unroll
        for (int off = 1; off < 32; off <<= 1) {
            int n = __shfl_up_sync(FM, run, off);
            if (lane >= off) run += n;
        }
        int e = run - s;
        cstart[lane * 4 + 0] = e;
        cstart[lane * 4 + 1] = e + v0;
        cstart[lane * 4 + 2] = e + v0 + v1;
        cstart[lane * 4 + 3] = e + v0 + v1 + v2;
        if (lane == 31) cstart[NC] = run;
    }
    __syncthreads();

    for (int k = 0; k < chk; k++) {
        int i = t * chk + k;
        int c = slab[i];
        int p = hist[c * NCH + t]++;
        g_perm[cstart[c] + p] = i;
    }
    __syncthreads();

    for (int r = t; r < B; r += NCH) {
        int c = slab[g_perm[r]];
        g_cs[r] = cstart[c];
        g_ce[r] = cstart[c + 1];
    }
}

// ------------------- permuted fp16 conversion (gather) ----------------------
__global__ __launch_bounds__(128) void to_fp16p(const float* __restrict__ e, int D) {
    const int r = blockIdx.x;
    const int pr = g_perm[r];
    const float4* src = (const float4*)(e + (size_t)pr * D);
    __half2* dst = (__half2*)(g_eth + (size_t)r * D);
    for (int d = threadIdx.x; d < D / 4; d += 128) {
        float4 v = src[d];
        dst[2 * d + 0] = __floats2half2_rn(v.x, v.y);
        dst[2 * d + 1] = __floats2half2_rn(v.z, v.w);
    }
}

// ------------------------ fused GEMM + reduction ----------------------------
// Triangular grid. 128x128 CTA tile, 16 warps (4m x 4n) of 32x32, BK=64,
// 3-stage pipeline fed by cp.async.bulk (128B per row-copy) + mbarrier.
// Per-thread arrive.expect_tx precedes each thread's own copy -> tx-count
// never underflows. Barrier arrive count = 256 (the issuing threads).
// 512 threads, 2 CTAs/SM = 32 warps/SM.
#define BK 64
#define PH 72                                  // smem pitch in halves (144 B)
#define STAGE_BYTES (2 * 128 * PH * 2)         // A + B stage footprint = 36864
#define NSTG 3
#define TS 132                                 // reduction tile pitch (floats)
#define OFF_MBAR (NSTG * STAGE_BYTES)          // 110592
#define SMEM_GEMM (OFF_MBAR + 64)              // 110656

__global__ __launch_bounds__(512, 2) void gemm_fused(int B, int D) {
    // linear -> triangular (by <= bx)
    const int t = blockIdx.x;
    int bx = (int)((sqrtf(8.0f * t + 1.0f) - 1.0f) * 0.5f);
    while ((bx + 1) * (bx + 2) / 2 <= t) bx++;
    while (bx * (bx + 1) / 2 > t) bx--;
    const int by = t - bx * (bx + 1) / 2;

    extern __shared__ float sm[];
    const uint32_t smb = smem_u32(sm);
    const uint32_t mb0 = smb + OFF_MBAR;           // mbar[s] = mb0 + 16*s
    const int tid  = threadIdx.x;
    const int warp = tid >> 5, lane = tid & 31;
    const int wm = warp & 3, wn = warp >> 2;       // 4 x 4 warp grid
    const int fr = lane >> 2, fq = lane & 3;

    const __half* gA = g_eth + (size_t)(by * 128) * D;
    const __half* gB = g_eth + (size_t)(bx * 128) * D;

    if (tid == 0) {
        MBAR_INIT(mb0 +  0, 256);
        MBAR_INIT(mb0 + 16, 256);
        MBAR_INIT(mb0 + 32, 256);
        FENCE_PROXY();                         // init visible to async proxy
    }
    __syncthreads();

    float acc[2][4][4];
#pragma unroll
    for (int mt = 0; mt < 2; mt++)
#pragma unroll
        for (int nt = 0; nt < 4; nt++)
#pragma unroll
            for (int e = 0; e < 4; e++) acc[mt][nt][e] = 0.0f;

    const int nK = D / BK;                          // 8

    // stage loader: threads 0..255 each arrive+expect(128) then issue their
    // own 128B bulk copy (one row of one operand). 256 arrivals + 32768 tx.
#define ISSUE_STAGE(s, k0)                                                     \
    do {                                                                       \
        if (tid < 256) {                                                       \
            const int rr = tid & 127, op = tid >> 7;                           \
            const uint32_t mb = mb0 + 16 * (s);                                \
            uint32_t dst = smb + (uint32_t)(s) * STAGE_BYTES                   \
                         + (uint32_t)op * (128 * PH * 2)                       \
                         + (uint32_t)rr * (PH * 2);                            \
            const __half* srcp = (op ? gB : gA) + (size_t)rr * D + (k0);       \
            MBAR_ARRIVE_EXPECT(mb, 128);                                       \
            bulk_cp(dst, srcp, 128, mb);                                       \
        }                                                                      \
    } while (0)

    ISSUE_STAGE(0, 0);
    ISSUE_STAGE(1, BK);

    const int a_lr = lane & 15, a_kh = lane >> 4;     // A: row 0-15, k-half
    const int b_gr = lane >> 3, b_rw = lane & 7;      // B: group 0-3, row 0-7

    for (int kt = 0; kt < nK; kt++) {
        MBAR_WAIT(mb0 + 16 * (kt % NSTG), (kt / NSTG) & 1);
        __syncthreads();   // all warps done reading stage (kt+2)%3 (at kt-1)
        if (kt + 2 < nK) ISSUE_STAGE((kt + 2) % NSTG, (kt + 2) * BK);

        const uint32_t asb = smb + (uint32_t)(kt % NSTG) * STAGE_BYTES;
        const uint32_t bsb = asb + 128 * PH * 2;

#pragma unroll
        for (int ks = 0; ks < 4; ks++) {
            const int k = ks * 16;
            uint32_t a[2][4], b[4][2];
#pragma unroll
            for (int mt = 0; mt < 2; mt++) {
                const int r = wm * 32 + mt * 16 + a_lr;
                ldm_x4(a[mt], asb + (uint32_t)(r * PH + k + a_kh * 8) * 2);
            }
#pragma unroll
            for (int np = 0; np < 2; np++) {
                const int c = wn * 32 + np * 16 + (b_gr >> 1) * 8 + b_rw;
                uint32_t rr2[4];
                ldm_x4(rr2, bsb + (uint32_t)(c * PH + k + (b_gr & 1) * 8) * 2);
                b[2 * np][0] = rr2[0]; b[2 * np][1] = rr2[1];
                b[2 * np + 1][0] = rr2[2]; b[2 * np + 1][1] = rr2[3];
            }
#pragma unroll
            for (int mt = 0; mt < 2; mt++)
#pragma unroll
                for (int nt = 0; nt < 4; nt++)
                    mma_f16_frag(acc[mt][nt], a[mt], b[nt]);
        }
    }
    __syncthreads();

    // ---- stage accumulator tile to smem ----
    float* tile = sm;                               // [128][TS]
#pragma unroll
    for (int mt = 0; mt < 2; mt++) {
#pragma unroll
        for (int nt = 0; nt < 4; nt++) {
            const int r0 = wm * 32 + mt * 16 + fr;
            const int c0 = wn * 32 + nt * 8 + 2 * fq;
            *(float2*)&tile[r0 * TS + c0]       = make_float2(acc[mt][nt][0], acc[mt][nt][1]);
            *(float2*)&tile[(r0 + 8) * TS + c0] = make_float2(acc[mt][nt][2], acc[mt][nt][3]);
        }
    }
    __syncthreads();

    // ---- concurrent passes, 2 threads per row/col (shfl-paired) ----
    if (tid < 256) {
        const int r = tid >> 1, h = tid & 1;
        const int gr = by * 128 + r;
        const int cs = g_cs[gr], ce = g_ce[gr];
        const int cbase = bx * 128 + h * 64;
        St st; st.init();
        const float* rowp = &tile[r * TS + h * 64];
#pragma unroll 4
        for (int j4 = 0; j4 < 16; j4++) {
            float4 v = *(const float4*)(rowp + j4 * 4);
            const int jg = cbase + j4 * 4;
            st.upd(v.x, jg + 0, cs, ce);
            st.upd(v.y, jg + 1, cs, ce);
            st.upd(v.z, jg + 2, cs, ce);
            st.upd(v.w, jg + 3, cs, ce);
        }
        st.mergeShfl(1);
        if (h == 0) st.storeL(&g_part[(size_t)(gr * 32 + bx) * 8]);
    } else if (bx != by) {
        const int u = tid - 256;
        const int c = u >> 1, h = u & 1;
        const int gc = bx * 128 + c;
        const int cs = g_cs[gc], ce = g_ce[gc];
        const int rbase = by * 128 + h * 64;
        St st; st.init();
#pragma unroll 4
        for (int r = 0; r < 64; r++)
            st.upd(tile[(h * 64 + r) * TS + c], rbase + r, cs, ce);
        st.mergeShfl(1);
        if (h == 0) st.storeL(&g_part[(size_t)(gc * 32 + by) * 8]);
    }
}

// ------------------------------- combine ------------------------------------
__global__ __launch_bounds__(256) void combine(float* __restrict__ out, int B) {
    const int lane = threadIdx.x & 31;
    const int w = threadIdx.x >> 5;
    const int row = blockIdx.x * 8 + w;
    const float4* p = (const float4*)&g_part[(size_t)(row * 32 + lane) * 8];
    float4 x0 = p[0], x1 = p[1];
    float pmin = x0.x, nmax = x0.y;
    float L1 = x0.z, L2 = x0.w, L3 = x1.x, L4 = x1.y;
    float M1 = L1, M2 = L2, M3 = L3, M4 = L4;
    const unsigned FM = 0xffffffffu;
#pragma unroll
    for (int o = 16; o > 0; o >>= 1) {
        pmin = fminf(pmin, __shfl_xor_sync(FM, pmin, o));
        nmax = fmaxf(nmax, __shfl_xor_sync(FM, nmax, o));
        M1 = fmaxf(M1, __shfl_xor_sync(FM, M1, o));
        M2 = fmaxf(M2, __shfl_xor_sync(FM, M2, o));
        M3 = fmaxf(M3, __shfl_xor_sync(FM, M3, o));
        M4 = fmaxf(M4, __shfl_xor_sync(FM, M4, o));
    }
    float e1 = expf(L1 - M1), e2 = expf(L2 - M2);
    float e3 = expf(L3 - M3), e4 = expf(L4 - M4);
#pragma unroll
    for (int o = 16; o > 0; o >>= 1) {
        e1 += __shfl_xor_sync(FM, e1, o);
        e2 += __shfl_xor_sync(FM, e2, o);
        e3 += __shfl_xor_sync(FM, e3, o);
        e4 += __shfl_xor_sync(FM, e4, o);
    }

    __shared__ float4 sh[8];
    if (lane == 0) {
        float se_pos;
        if (M1 > NEG_INF)      se_pos = M1 + logf(e1);
        else if (M2 > NEG_INF) se_pos = M2 + logf(e2);
        else se_pos = -SCALE_C * fmaxf(OPT_P - pmin, 0.0f) * (pmin - MARGIN_P);
        float se_neg;
        if (M3 > NEG_INF)      se_neg = M3 + logf(e3);
        else if (M4 > NEG_INF) se_neg = M4 + logf(e4);
        else if (nmax > NEG_INF)
            se_neg = SCALE_C * fmaxf(nmax - OPT_N, 0.0f) * (nmax - MARGIN_N);
        else se_neg = 0.0f;

        float z = se_pos + se_neg;
        float pl = (z > 0.0f) ? (z + log1pf(expf(-z))) : log1pf(expf(z));
        float lowf  = (pmin > nmax) ? 1.0f : 0.0f;
        float medf  = (lowf != 0.0f && pmin > MARGIN_P) ? 1.0f : 0.0f;
        float highf = (medf != 0.0f && nmax < MARGIN_N) ? 1.0f : 0.0f;
        sh[w] = make_float4(pl, lowf, medf, highf);
    }
    __syncthreads();

    __shared__ int sticket;
    if (threadIdx.x == 0) {
        float4 a = sh[0];
#pragma unroll
        for (int i = 1; i < 8; i++) {
            float4 b = sh[i];
            a.x += b.x; a.y += b.y; a.z += b.z; a.w += b.w;
        }
        g_bsum[blockIdx.x] = a;
        __threadfence();
        sticket = atomicAdd(&g_cnt, 1);
    }
    __syncthreads();

    const int nb = B / 8;                      // 512 blocks
    if (sticket == nb - 1) {                   // last block finishes the job
        __shared__ float4 sh4[256];
        const int tid = threadIdx.x;
        float4 a = __ldcg(&g_bsum[tid]);
        float4 b = __ldcg(&g_bsum[tid + 256]);
        sh4[tid] = make_float4(a.x + b.x, a.y + b.y, a.z + b.z, a.w + b.w);
        __syncthreads();
        for (int off = 128; off > 0; off >>= 1) {
            if (tid < off) {
                float4 x = sh4[tid], y = sh4[tid + off];
                sh4[tid] = make_float4(x.x + y.x, x.y + y.y, x.z + y.z, x.w + y.w);
            }
            __syncthreads();
        }
        if (tid == 0) {
            float inv = 1.0f / (float)B;
            out[0] = sh4[0].x * inv;
            out[1] = sh4[0].y * inv;
            out[2] = sh4[0].z * inv;
            out[3] = sh4[0].w * inv;
            g_cnt = 0;                         // reset for next graph replay
        }
    }
}

// ------------------------------- launch ------------------------------------
extern "C" void kernel_launch(void* const* d_in, const int* in_sizes, int n_in,
                              void* d_out, int out_size) {
    const float* emb = (const float*)d_in[0];
    const void*  lab = d_in[1];
    const int B = in_sizes[1];
    const int D = in_sizes[0] / B;

    cudaFuncSetAttribute(gemm_fused, cudaFuncAttributeMaxDynamicSharedMemorySize, SMEM_GEMM);
    cudaFuncSetAttribute(sort_labels, cudaFuncAttributeMaxDynamicSharedMemorySize, SORT_SMEM);

    sort_labels<<<1, 256, SORT_SMEM>>>(lab, B);
    to_fp16p<<<B, 128>>>(emb, D);

    const int nb = B / 128;
    const int nT = nb * (nb + 1) / 2;           // 528 triangular blocks
    gemm_fused<<<nT, 512, SMEM_GEMM>>>(B, D);

    combine<<<B / 8, 256>>>((float*)d_out, B);
}

// round 17
// speedup vs baseline: 1.1120x; 1.1120x over previous
#include <cuda_runtime.h>
#include <cuda.h>
#include <cuda_bf16.h>
#include <cuda_fp16.h>
#include <math.h>
#include <stdint.h>

// ---------------------------------------------------------------------------
// CircleLoss, TMA tensor-map edition:
//   1) sort_labels : parallel dtype detect + warp-scan stable counting sort
//   2) to_fp16p    : gather-permuted E -> fp16 scratch
//   3) gemm_fused  : triangular grid (528 CTAs), 512 threads (16 warps of
//                    32x32), BK=64, 3-stage pipeline fed by 2x 16KB TMA
//                    tensor-map loads per stage (SW128 swizzle), swizzled
//                    ldmatrix feeds, row+mirror-col L-form partials.
//   4) combine     : 512 x 256, branch-free warp LSE, ticketed last block
//                    folds block sums -> out[0..3]
// ---------------------------------------------------------------------------

#define MAXB 4096
#define MAXD 512

__device__ __half g_eth[MAXB * MAXD];          // 4 MB permuted fp16 embeddings
__device__ float  g_part[MAXB * 32 * 8];       // 4.2 MB partial states (L-form)
__device__ float4 g_bsum[MAXB / 8];            // per-combine-block sums
__device__ int    g_perm[MAXB];
__device__ int    g_cs[MAXB];
__device__ int    g_ce[MAXB];
__device__ int    g_cnt = 0;                   // combine completion ticket

#define SCALE_C   32.0f
#define MARGIN_P  0.75f
#define MARGIN_N  0.25f
#define OPT_P     1.25f
#define OPT_N     (-0.25f)
#define THETA_C   0.25f
#define NEG_INF   (-INFINITY)

// ------------------------------ helpers ------------------------------------
__device__ __forceinline__ uint32_t smem_u32(const void* p) {
    uint32_t a;
    asm("{ .reg .u64 t; cvta.to.shared.u64 t, %1; cvt.u32.u64 %0, t; }"
        : "=r"(a) : "l"(p));
    return a;
}
#define MBAR_INIT(a, c) \
    asm volatile("mbarrier.init.shared.b64 [%0], %1;" :: "r"(a), "r"((uint32_t)(c)) : "memory")
#define MBAR_ARRIVE_EXPECT(a, bytes) \
    asm volatile("mbarrier.arrive.expect_tx.shared.b64 _, [%0], %1;" \
                 :: "r"(a), "r"((uint32_t)(bytes)) : "memory")
#define MBAR_WAIT(a, par) do {                                                  \
    uint32_t _m = (a), _p = (par);                                              \
    asm volatile("{\n\t.reg .pred P;\n\tWL_%=:\n\t"                             \
        "mbarrier.try_wait.parity.acquire.cta.shared::cta.b64 P, [%0], %1, 0x989680;\n\t" \
        "@P bra.uni WD_%=;\n\tbra.uni WL_%=;\n\tWD_%=:\n\t}"                    \
        :: "r"(_m), "r"(_p) : "memory");                                        \
} while (0)
#define FENCE_PROXY() asm volatile("fence.proxy.async.shared::cta;" ::: "memory")
__device__ __forceinline__ void tma2d(uint32_t dst, const void* map,
                                      int x, int y, uint32_t mbar) {
    asm volatile(
        "cp.async.bulk.tensor.2d.shared::cta.global.tile.mbarrier::complete_tx::bytes "
        "[%0], [%1, {%2, %3}], [%4];"
        :: "r"(dst), "l"(map), "r"(x), "r"(y), "r"(mbar) : "memory");
}
__device__ __forceinline__ void ldm_x4(uint32_t* r, uint32_t addr) {
    asm volatile("ldmatrix.sync.aligned.m8n8.x4.shared.b16 {%0,%1,%2,%3}, [%4];"
        : "=r"(r[0]), "=r"(r[1]), "=r"(r[2]), "=r"(r[3]) : "r"(addr));
}
__device__ __forceinline__ void mma_f16_frag(float* d, const uint32_t* a, const uint32_t* b) {
    asm volatile(
        "mma.sync.aligned.m16n8k16.row.col.f32.f16.f16.f32 "
        "{%0,%1,%2,%3}, {%4,%5,%6,%7}, {%8,%9}, {%0,%1,%2,%3};"
        : "+f"(d[0]), "+f"(d[1]), "+f"(d[2]), "+f"(d[3])
        : "r"(a[0]), "r"(a[1]), "r"(a[2]), "r"(a[3]), "r"(b[0]), "r"(b[1]));
}
// byte offset inside a SW128 128B-row tile for (row r, 16B-aligned kb)
__device__ __forceinline__ uint32_t sw_off(uint32_t r, uint32_t kb) {
    return r * 128u + (kb ^ ((r & 7u) << 4));
}
__device__ __forceinline__ void lse_add(float& m, float& s, float v) {
    if (v > m) { s = s * expf(m - v) + 1.0f; m = v; }
    else       { s += expf(v - m); }
}
__device__ __forceinline__ void lse_merge(float& m1, float& s1, float m2, float s2) {
    if (m2 == NEG_INF) return;
    if (m2 > m1) { s1 = s1 * expf(m1 - m2) + s2; m1 = m2; }
    else         { s1 += s2 * expf(m2 - m1); }
}
__device__ __forceinline__ float lse_close(float m, float s) {
    return (m == NEG_INF) ? NEG_INF : m + logf(s);
}

struct St {
    float pmin, nmax, m1, s1, m2, s2, m3, s3, m4, s4;
    __device__ __forceinline__ void init() {
        pmin = INFINITY; nmax = NEG_INF;
        m1 = m2 = m3 = m4 = NEG_INF; s1 = s2 = s3 = s4 = 0.f;
    }
    __device__ __forceinline__ void upd(float s, int j, int cs, int ce) {
        if (j >= cs && j < ce) {                       // positive (incl. self)
            pmin = fminf(pmin, s);
            if (s < MARGIN_P) {
                float ip = -SCALE_C * fmaxf(OPT_P - s, 0.0f) * (s - MARGIN_P);
                lse_add(m2, s2, ip);
                if (s + THETA_C < MARGIN_P) lse_add(m1, s1, ip);
            }
        } else {
            nmax = fmaxf(nmax, s);
            if (s > MARGIN_N) {
                float in_ = SCALE_C * fmaxf(s - OPT_N, 0.0f) * (s - MARGIN_N);
                lse_add(m4, s4, in_);
                if (s - THETA_C > MARGIN_N) lse_add(m3, s3, in_);
            }
        }
    }
    __device__ __forceinline__ void mergeShfl(int xorMask) {
        const unsigned FM = 0xffffffffu;
        pmin = fminf(pmin, __shfl_xor_sync(FM, pmin, xorMask));
        nmax = fmaxf(nmax, __shfl_xor_sync(FM, nmax, xorMask));
        float mm, ss;
        mm = __shfl_xor_sync(FM, m1, xorMask); ss = __shfl_xor_sync(FM, s1, xorMask);
        lse_merge(m1, s1, mm, ss);
        mm = __shfl_xor_sync(FM, m2, xorMask); ss = __shfl_xor_sync(FM, s2, xorMask);
        lse_merge(m2, s2, mm, ss);
        mm = __shfl_xor_sync(FM, m3, xorMask); ss = __shfl_xor_sync(FM, s3, xorMask);
        lse_merge(m3, s3, mm, ss);
        mm = __shfl_xor_sync(FM, m4, xorMask); ss = __shfl_xor_sync(FM, s4, xorMask);
        lse_merge(m4, s4, mm, ss);
    }
    // L-form store: 8 floats = pmin, nmax, L1..L4, pad, pad
    __device__ __forceinline__ void storeL(float* p) const {
        ((float4*)p)[0] = make_float4(pmin, nmax, lse_close(m1, s1), lse_close(m2, s2));
        ((float4*)p)[1] = make_float4(lse_close(m3, s3), lse_close(m4, s4), 0.f, 0.f);
    }
};

// ---------------------- parallel deterministic sort -------------------------
#define NC 128
#define NCH 256
#define OFF_HIST  (MAXB * 4)
#define OFF_CTOT  (OFF_HIST + NC * NCH * 2)
#define OFF_CST   (OFF_CTOT + NC * 4)
#define SORT_SMEM (OFF_CST + (NC + 1) * 4 + 64)

__global__ void sort_labels(const void* __restrict__ lab, int B) {
    extern __shared__ char sms[];
    int* slab = (int*)sms;
    unsigned short* hist = (unsigned short*)(sms + OFF_HIST);
    int* ctot   = (int*)(sms + OFF_CTOT);
    int* cstart = (int*)(sms + OFF_CST);

    const int t = threadIdx.x;
    const int lane = t & 31, w = t >> 5;
    const int chk = B / NCH;
    const unsigned FM = 0xffffffffu;

    __shared__ int is64;
    {
        const int nProbe = (B < 64) ? B : 64;
        int ok = 1;
        if (t < nProbe) {
            long long v = ((const long long*)lab)[t];
            ok = (v >= 0 && v < (long long)B);
        }
        unsigned m0 = __ballot_sync(FM, ok);
        __shared__ unsigned mball[2];
        if (w < 2 && lane == 0) mball[w] = m0;
        __syncthreads();
        if (t == 0) is64 = (mball[0] == FM) && (mball[1] == FM);
        __syncthreads();
    }
    if (is64) {
        const long long* p = (const long long*)lab;
        for (int i = t; i < B; i += NCH) slab[i] = (int)p[i];
    } else {
        const int* p = (const int*)lab;
        for (int i = t; i < B; i += NCH) slab[i] = p[i];
    }
    for (int i = t; i < NC * NCH / 2; i += NCH) ((uint32_t*)hist)[i] = 0;
    __syncthreads();

    for (int k = 0; k < chk; k++) hist[slab[t * chk + k] * NCH + t]++;
    __syncthreads();

    for (int ci = 0; ci < NC / 8; ci++) {
        const int c = w + 8 * ci;
        uint32_t* hp = (uint32_t*)&hist[c * NCH + lane * 8];
        uint4 q = *(uint4*)hp;
        unsigned v[8] = { q.x & 0xffffu, q.x >> 16, q.y & 0xffffu, q.y >> 16,
                          q.z & 0xffffu, q.z >> 16, q.w & 0xffffu, q.w >> 16 };
        unsigned e[8]; unsigned s = 0;
#pragma unroll
        for (int j = 0; j < 8; j++) { e[j] = s; s += v[j]; }
        unsigned run = s;
#pragma unroll
        for (int off = 1; off < 32; off <<= 1) {
            unsigned n = __shfl_up_sync(FM, run, off);
            if (lane >= off) run += n;
        }
        const unsigned laneExc = run - s;
#pragma unroll
        for (int j = 0; j < 8; j++) e[j] += laneExc;
        *(uint4*)hp = make_uint4(e[0] | (e[1] << 16), e[2] | (e[3] << 16),
                                 e[4] | (e[5] << 16), e[6] | (e[7] << 16));
        if (lane == 31) ctot[c] = (int)run;
    }
    __syncthreads();

    if (w == 0) {
        int v0 = ctot[lane * 4 + 0], v1 = ctot[lane * 4 + 1];
        int v2 = ctot[lane * 4 + 2], v3 = ctot[lane * 4 + 3];
        int s = v0 + v1 + v2 + v3;
        int run = s;
#pragma unroll
        for (int off = 1; off < 32; off <<= 1) {
            int n = __shfl_up_sync(FM, run, off);
            if (lane >= off) run += n;
        }
        int e = run - s;
        cstart[lane * 4 + 0] = e;
        cstart[lane * 4 + 1] = e + v0;
        cstart[lane * 4 + 2] = e + v0 + v1;
        cstart[lane * 4 + 3] = e + v0 + v1 + v2;
        if (lane == 31) cstart[NC] = run;
    }
    __syncthreads();

    for (int k = 0; k < chk; k++) {
        int i = t * chk + k;
        int c = slab[i];
        int p = hist[c * NCH + t]++;
        g_perm[cstart[c] + p] = i;
    }
    __syncthreads();

    for (int r = t; r < B; r += NCH) {
        int c = slab[g_perm[r]];
        g_cs[r] = cstart[c];
        g_ce[r] = cstart[c + 1];
    }
}

// ------------------- permuted fp16 conversion (gather) ----------------------
__global__ __launch_bounds__(128) void to_fp16p(const float* __restrict__ e, int D) {
    const int r = blockIdx.x;
    const int pr = g_perm[r];
    const float4* src = (const float4*)(e + (size_t)pr * D);
    __half2* dst = (__half2*)(g_eth + (size_t)r * D);
    for (int d = threadIdx.x; d < D / 4; d += 128) {
        float4 v = src[d];
        dst[2 * d + 0] = __floats2half2_rn(v.x, v.y);
        dst[2 * d + 1] = __floats2half2_rn(v.z, v.w);
    }
}

// ------------------------ fused GEMM + reduction ----------------------------
// Triangular grid. 128x128 CTA tile, 16 warps (4m x 4n) of 32x32, BK=64,
// 3-stage pipeline: 2 TMA tensor-map loads (16KB each, SW128) per stage.
// 512 threads, 2 CTAs/SM = 32 warps/SM.
#define BK 64
#define OPTILE 16384                           // 128 rows x 128B, swizzled
#define STAGE_BYTES (2 * OPTILE)               // A + B = 32768
#define NSTG 3
#define TS 132                                 // reduction tile pitch (floats)
#define SMEM_GEMM (1024 + NSTG * STAGE_BYTES + 64)   // align + stages + mbars

__global__ __launch_bounds__(512, 2) void gemm_fused(
        const __grid_constant__ CUtensorMap tmap, int B, int D) {
    // linear -> triangular (by <= bx)
    const int t = blockIdx.x;
    int bx = (int)((sqrtf(8.0f * t + 1.0f) - 1.0f) * 0.5f);
    while ((bx + 1) * (bx + 2) / 2 <= t) bx++;
    while (bx * (bx + 1) / 2 > t) bx--;
    const int by = t - bx * (bx + 1) / 2;

    extern __shared__ float sm[];
    const uint32_t smb = smem_u32(sm);
    const uint32_t alb = (smb + 1023u) & ~1023u;   // 1KB-aligned stage base
    const uint32_t mb0 = alb + NSTG * STAGE_BYTES; // mbar[s] = mb0 + 16*s
    const int tid  = threadIdx.x;
    const int warp = tid >> 5, lane = tid & 31;
    const int wm = warp & 3, wn = warp >> 2;       // 4 x 4 warp grid
    const int fr = lane >> 2, fq = lane & 3;

    if (tid == 0) {
        MBAR_INIT(mb0 +  0, 1);
        MBAR_INIT(mb0 + 16, 1);
        MBAR_INIT(mb0 + 32, 1);
        FENCE_PROXY();                         // init visible to async proxy
    }
    __syncthreads();

    float acc[2][4][4];
#pragma unroll
    for (int mt = 0; mt < 2; mt++)
#pragma unroll
        for (int nt = 0; nt < 4; nt++)
#pragma unroll
            for (int e = 0; e < 4; e++) acc[mt][nt][e] = 0.0f;

    const int nK = D / BK;                          // 8

    // one thread: expect 32KB then issue both 16KB tensor loads
#define ISSUE_STAGE(s, k0)                                                     \
    do {                                                                       \
        if (tid == 0) {                                                        \
            const uint32_t mb = mb0 + 16 * (s);                                \
            const uint32_t ab = alb + (uint32_t)(s) * STAGE_BYTES;             \
            MBAR_ARRIVE_EXPECT(mb, STAGE_BYTES);                               \
            tma2d(ab, &tmap, (k0), by * 128, mb);                              \
            tma2d(ab + OPTILE, &tmap, (k0), bx * 128, mb);                     \
        }                                                                      \
    } while (0)

    ISSUE_STAGE(0, 0);
    ISSUE_STAGE(1, BK);

    const int a_lr = lane & 15, a_kh = lane >> 4;     // A: row 0-15, k-half
    const int b_gr = lane >> 3, b_rw = lane & 7;      // B: group 0-3, row 0-7

    for (int kt = 0; kt < nK; kt++) {
        MBAR_WAIT(mb0 + 16 * (kt % NSTG), (kt / NSTG) & 1);
        __syncthreads();   // all warps done reading stage (kt+2)%3 (at kt-1)
        if (kt + 2 < nK) ISSUE_STAGE((kt + 2) % NSTG, (kt + 2) * BK);

        const uint32_t asb = alb + (uint32_t)(kt % NSTG) * STAGE_BYTES;
        const uint32_t bsb = asb + OPTILE;

#pragma unroll
        for (int ks = 0; ks < 4; ks++) {
            const uint32_t kbA = (uint32_t)(ks * 32 + a_kh * 16);
            const uint32_t kbB0 = (uint32_t)(ks * 32 + (b_gr & 1) * 16);
            uint32_t a[2][4], b[4][2];
#pragma unroll
            for (int mt = 0; mt < 2; mt++) {
                const uint32_t r = (uint32_t)(wm * 32 + mt * 16 + a_lr);
                ldm_x4(a[mt], asb + sw_off(r, kbA));
            }
#pragma unroll
            for (int np = 0; np < 2; np++) {
                const uint32_t c = (uint32_t)(wn * 32 + np * 16 + (b_gr >> 1) * 8 + b_rw);
                uint32_t rr2[4];
                ldm_x4(rr2, bsb + sw_off(c, kbB0));
                b[2 * np][0] = rr2[0]; b[2 * np][1] = rr2[1];
                b[2 * np + 1][0] = rr2[2]; b[2 * np + 1][1] = rr2[3];
            }
#pragma unroll
            for (int mt = 0; mt < 2; mt++)
#pragma unroll
                for (int nt = 0; nt < 4; nt++)
                    mma_f16_frag(acc[mt][nt], a[mt], b[nt]);
        }
    }
    __syncthreads();

    // ---- stage accumulator tile to smem (reuses stage area) ----
    float* tile = (float*)(size_t)(alb - smb + (char*)sm);   // aligned base
#pragma unroll
    for (int mt = 0; mt < 2; mt++) {
#pragma unroll
        for (int nt = 0; nt < 4; nt++) {
            const int r0 = wm * 32 + mt * 16 + fr;
            const int c0 = wn * 32 + nt * 8 + 2 * fq;
            *(float2*)&tile[r0 * TS + c0]       = make_float2(acc[mt][nt][0], acc[mt][nt][1]);
            *(float2*)&tile[(r0 + 8) * TS + c0] = make_float2(acc[mt][nt][2], acc[mt][nt][3]);
        }
    }
    __syncthreads();

    // ---- concurrent passes, 2 threads per row/col (shfl-paired) ----
    if (tid < 256) {
        const int r = tid >> 1, h = tid & 1;
        const int gr = by * 128 + r;
        const int cs = g_cs[gr], ce = g_ce[gr];
        const int cbase = bx * 128 + h * 64;
        St st; st.init();
        const float* rowp = &tile[r * TS + h * 64];
#pragma unroll 4
        for (int j4 = 0; j4 < 16; j4++) {
            float4 v = *(const float4*)(rowp + j4 * 4);
            const int jg = cbase + j4 * 4;
            st.upd(v.x, jg + 0, cs, ce);
            st.upd(v.y, jg + 1, cs, ce);
            st.upd(v.z, jg + 2, cs, ce);
            st.upd(v.w, jg + 3, cs, ce);
        }
        st.mergeShfl(1);
        if (h == 0) st.storeL(&g_part[(size_t)(gr * 32 + bx) * 8]);
    } else if (bx != by) {
        const int u = tid - 256;
        const int c = u >> 1, h = u & 1;
        const int gc = bx * 128 + c;
        const int cs = g_cs[gc], ce = g_ce[gc];
        const int rbase = by * 128 + h * 64;
        St st; st.init();
#pragma unroll 4
        for (int r = 0; r < 64; r++)
            st.upd(tile[(h * 64 + r) * TS + c], rbase + r, cs, ce);
        st.mergeShfl(1);
        if (h == 0) st.storeL(&g_part[(size_t)(gc * 32 + by) * 8]);
    }
}

// ------------------------------- combine ------------------------------------
__global__ __launch_bounds__(256) void combine(float* __restrict__ out, int B) {
    const int lane = threadIdx.x & 31;
    const int w = threadIdx.x >> 5;
    const int row = blockIdx.x * 8 + w;
    const float4* p = (const float4*)&g_part[(size_t)(row * 32 + lane) * 8];
    float4 x0 = p[0], x1 = p[1];
    float pmin = x0.x, nmax = x0.y;
    float L1 = x0.z, L2 = x0.w, L3 = x1.x, L4 = x1.y;
    float M1 = L1, M2 = L2, M3 = L3, M4 = L4;
    const unsigned FM = 0xffffffffu;
#pragma unroll
    for (int o = 16; o > 0; o >>= 1) {
        pmin = fminf(pmin, __shfl_xor_sync(FM, pmin, o));
        nmax = fmaxf(nmax, __shfl_xor_sync(FM, nmax, o));
        M1 = fmaxf(M1, __shfl_xor_sync(FM, M1, o));
        M2 = fmaxf(M2, __shfl_xor_sync(FM, M2, o));
        M3 = fmaxf(M3, __shfl_xor_sync(FM, M3, o));
        M4 = fmaxf(M4, __shfl_xor_sync(FM, M4, o));
    }
    float e1 = expf(L1 - M1), e2 = expf(L2 - M2);
    float e3 = expf(L3 - M3), e4 = expf(L4 - M4);
#pragma unroll
    for (int o = 16; o > 0; o >>= 1) {
        e1 += __shfl_xor_sync(FM, e1, o);
        e2 += __shfl_xor_sync(FM, e2, o);
        e3 += __shfl_xor_sync(FM, e3, o);
        e4 += __shfl_xor_sync(FM, e4, o);
    }

    __shared__ float4 sh[8];
    if (lane == 0) {
        float se_pos;
        if (M1 > NEG_INF)      se_pos = M1 + logf(e1);
        else if (M2 > NEG_INF) se_pos = M2 + logf(e2);
        else se_pos = -SCALE_C * fmaxf(OPT_P - pmin, 0.0f) * (pmin - MARGIN_P);
        float se_neg;
        if (M3 > NEG_INF)      se_neg = M3 + logf(e3);
        else if (M4 > NEG_INF) se_neg = M4 + logf(e4);
        else if (nmax > NEG_INF)
            se_neg = SCALE_C * fmaxf(nmax - OPT_N, 0.0f) * (nmax - MARGIN_N);
        else se_neg = 0.0f;

        float z = se_pos + se_neg;
        float pl = (z > 0.0f) ? (z + log1pf(expf(-z))) : log1pf(expf(z));
        float lowf  = (pmin > nmax) ? 1.0f : 0.0f;
        float medf  = (lowf != 0.0f && pmin > MARGIN_P) ? 1.0f : 0.0f;
        float highf = (medf != 0.0f && nmax < MARGIN_N) ? 1.0f : 0.0f;
        sh[w] = make_float4(pl, lowf, medf, highf);
    }
    __syncthreads();

    __shared__ int sticket;
    if (threadIdx.x == 0) {
        float4 a = sh[0];
#pragma unroll
        for (int i = 1; i < 8; i++) {
            float4 b = sh[i];
            a.x += b.x; a.y += b.y; a.z += b.z; a.w += b.w;
        }
        g_bsum[blockIdx.x] = a;
        __threadfence();
        sticket = atomicAdd(&g_cnt, 1);
    }
    __syncthreads();

    const int nb = B / 8;                      // 512 blocks
    if (sticket == nb - 1) {                   // last block finishes the job
        __shared__ float4 sh4[256];
        const int tid = threadIdx.x;
        float4 a = __ldcg(&g_bsum[tid]);
        float4 b = __ldcg(&g_bsum[tid + 256]);
        sh4[tid] = make_float4(a.x + b.x, a.y + b.y, a.z + b.z, a.w + b.w);
        __syncthreads();
        for (int off = 128; off > 0; off >>= 1) {
            if (tid < off) {
                float4 x = sh4[tid], y = sh4[tid + off];
                sh4[tid] = make_float4(x.x + y.x, x.y + y.y, x.z + y.z, x.w + y.w);
            }
            __syncthreads();
        }
        if (tid == 0) {
            float inv = 1.0f / (float)B;
            out[0] = sh4[0].x * inv;
            out[1] = sh4[0].y * inv;
            out[2] = sh4[0].z * inv;
            out[3] = sh4[0].w * inv;
            g_cnt = 0;                         // reset for next graph replay
        }
    }
}

// ------------------------------- launch ------------------------------------
typedef CUresult (*EncTiledFn)(
    CUtensorMap*, CUtensorMapDataType, cuuint32_t, void*,
    const cuuint64_t*, const cuuint64_t*, const cuuint32_t*, const cuuint32_t*,
    CUtensorMapInterleave, CUtensorMapSwizzle, CUtensorMapL2promotion,
    CUtensorMapFloatOOBfill);

extern "C" void kernel_launch(void* const* d_in, const int* in_sizes, int n_in,
                              void* d_out, int out_size) {
    const float* emb = (const float*)d_in[0];
    const void*  lab = d_in[1];
    const int B = in_sizes[1];
    const int D = in_sizes[0] / B;

    cudaFuncSetAttribute(gemm_fused, cudaFuncAttributeMaxDynamicSharedMemorySize, SMEM_GEMM);
    cudaFuncSetAttribute(sort_labels, cudaFuncAttributeMaxDynamicSharedMemorySize, SORT_SMEM);

    // build the tensor map (host-side, deterministic, capture-safe)
    CUtensorMap tmap;
    {
        void* fn = nullptr;
        cudaDriverEntryPointQueryResult qs;
        cudaGetDriverEntryPoint("cuTensorMapEncodeTiled", &fn,
                                cudaEnableDefault, &qs);
        void* ethp = nullptr;
        cudaGetSymbolAddress(&ethp, g_eth);
        cuuint64_t dims[2]    = { (cuuint64_t)D, (cuuint64_t)B };
        cuuint64_t strides[1] = { (cuuint64_t)D * 2 };
        cuuint32_t box[2]     = { 64, 128 };
        cuuint32_t estr[2]    = { 1, 1 };
        ((EncTiledFn)fn)(&tmap, CU_TENSOR_MAP_DATA_TYPE_UINT16, 2, ethp,
                         dims, strides, box, estr,
                         CU_TENSOR_MAP_INTERLEAVE_NONE,
                         CU_TENSOR_MAP_SWIZZLE_128B,
                         CU_TENSOR_MAP_L2_PROMOTION_L2_128B,
                         CU_TENSOR_MAP_FLOAT_OOB_FILL_NONE);
    }

    sort_labels<<<1, 256, SORT_SMEM>>>(lab, B);
    to_fp16p<<<B, 128>>>(emb, D);

    const int nb = B / 128;
    const int nT = nb * (nb + 1) / 2;           // 528 triangular blocks
    gemm_fused<<<nT, 512, SMEM_GEMM>>>(tmap, B, D);

    combine<<<B / 8, 256>>>((float*)d_out, B);
}